// round 14
// baseline (speedup 1.0000x reference)
#include <cuda_runtime.h>
#include <cstdint>
#include <math.h>

#define NP    2048
#define DFEAT 256
#define BTM   128
#define BTN   256
#define NBX   (NP / BTN)       // 8
#define NBY   (NP / BTM)       // 16
#define NCTAS (NBX * NBY)      // 128 -> 1 CTA/SM, co-resident single wave
#define LOG2E 1.4426950408889634f

// K (256 int8) streamed in 2 chunks of 128B; rows padded to 144B
#define ROWC    144
#define A_CHUNK (BTM * ROWC)   // 18432
#define B_CHUNK (BTN * ROWC)   // 36864
#define SM_A0   0
#define SM_A1   A_CHUNK
#define SM_B0   (2 * A_CHUNK)
#define SM_B1   (2 * A_CHUNK + B_CHUNK)
#define SM_SA   (2 * A_CHUNK + 2 * B_CHUNK)   // sA[128] floats
#define SM_SB   (SM_SA + 512)                 // sB[256] floats
#define SM_RP   (SM_SB + 1024)                // rpart[4][128]
#define SM_CP   (SM_RP + 2048)                // cpart[4][256]
#define SM_RED  (SM_CP + 4096)                // red[512]
#define SMEM_TOTAL (SM_RED + 2048)            // 120320 B

// -------- device scratch --------
__device__ __align__(16) int8_t g_Aq[NP * DFEAT];
__device__ __align__(16) int8_t g_Bq[NP * DFEAT];
__device__ float g_SA[NP];
__device__ float g_SB[NP];
__device__ float g_Row[NP];     // zeroed each replay in phase 1
__device__ float g_Col[NP];
__device__ float g_Dpos[NP];
__device__ float g_ExclR[NP];   // p>=1024 never written, stays 0
__device__ float g_ExclC[NP];
__device__ unsigned int g_bar  = 0;   // monotone grid barrier
__device__ unsigned int g_done = 0;   // monotone finalize ticket

static __device__ __forceinline__ uint32_t smem_u32(const void* p) {
    return (uint32_t)__cvta_generic_to_shared((void*)p);
}

static __device__ __forceinline__ void cpasync16(uint32_t dst, const void* src) {
    asm volatile("cp.async.cg.shared.global [%0], [%1], 16;"
                 :: "r"(dst), "l"(src));
}
#define CP_COMMIT() asm volatile("cp.async.commit_group;" ::: "memory")
#define CP_WAIT(N)  asm volatile("cp.async.wait_group %0;" :: "n"(N) : "memory")

static __device__ __forceinline__ void ldsm_x4(uint32_t* r, uint32_t addr) {
    asm volatile("ldmatrix.sync.aligned.m8n8.x4.shared.b16 {%0,%1,%2,%3}, [%4];"
                 : "=r"(r[0]), "=r"(r[1]), "=r"(r[2]), "=r"(r[3]) : "r"(addr));
}

static __device__ __forceinline__ void imma16832(int* c, const uint32_t* a,
                                                 const uint32_t* b) {
    asm volatile(
        "mma.sync.aligned.m16n8k32.row.col.s32.s8.s8.s32 "
        "{%0,%1,%2,%3}, {%4,%5,%6,%7}, {%8,%9}, {%0,%1,%2,%3};"
        : "+r"(c[0]), "+r"(c[1]), "+r"(c[2]), "+r"(c[3])
        : "r"(a[0]), "r"(a[1]), "r"(a[2]), "r"(a[3]), "r"(b[0]), "r"(b[1]));
}

static __device__ __forceinline__ float ex2f(float a) {
    float r;
    asm("ex2.approx.f32 %0, %1;" : "=f"(r) : "f"(a));
    return r;
}

// ---------------------------------------------------------------------------
// Single fused kernel:
//   phase 1: each CTA quantizes 32 rows of X (int8 + row scale) and zeroes
//            its slice of g_Row/g_Col.
//   grid barrier (monotone ticket; all 128 CTAs co-resident).
//   phase 2: R13-validated IMMA gemm + unmasked exp epilogue + exclusion
//            side loops; partials REDG'd into g_Row/g_Col.
//   last CTA: slim finalize.
// ---------------------------------------------------------------------------
__global__ __launch_bounds__(512, 1)
void sml_fused(const float* __restrict__ X, float* __restrict__ out) {
    extern __shared__ char smem[];
    const uint32_t sbase = smem_u32(smem);
    float* sA_s  = (float*)(smem + SM_SA);
    float* sB_s  = (float*)(smem + SM_SB);
    float* rpart = (float*)(smem + SM_RP);
    float* cpart = (float*)(smem + SM_CP);

    const int tid = threadIdx.x;
    const int wid = tid >> 5;
    const int l   = tid & 31;
    const int wm  = wid & 3;
    const int wn  = wid >> 2;
    const int bx = blockIdx.x, by = blockIdx.y;
    const int r0 = by * BTM, c0 = bx * BTN;
    const int L  = by * NBX + bx;          // 0..127

    // ================= phase 1: quantize rows L*32 .. L*32+31 ==============
#pragma unroll
    for (int rr = 0; rr < 2; rr++) {
        const int gw = L * 32 + wid * 2 + rr;   // X row
        const float4* src = (const float4*)X + (size_t)gw * 64;
        const float4 v0 = src[l];
        const float4 v1 = src[l + 32];

        float m = fmaxf(fmaxf(fabsf(v0.x), fabsf(v0.y)),
                        fmaxf(fabsf(v0.z), fabsf(v0.w)));
        m = fmaxf(m, fmaxf(fmaxf(fabsf(v1.x), fabsf(v1.y)),
                           fmaxf(fabsf(v1.z), fabsf(v1.w))));
#pragma unroll
        for (int mk = 16; mk > 0; mk >>= 1)
            m = fmaxf(m, __shfl_xor_sync(0xFFFFFFFFu, m, mk));
        m = fmaxf(m, 1e-20f);
        const float rs = 127.0f / m;

        const int p = gw >> 1;
        int8_t* dstrow;
        float* sdst;
        if (gw & 1) { dstrow = g_Bq + (size_t)p * DFEAT; sdst = g_SB; }
        else        { dstrow = g_Aq + (size_t)p * DFEAT; sdst = g_SA; }

        uint32_t* d32 = (uint32_t*)dstrow;
        {
            int q0 = __float2int_rn(v0.x * rs), q1 = __float2int_rn(v0.y * rs);
            int q2 = __float2int_rn(v0.z * rs), q3 = __float2int_rn(v0.w * rs);
            d32[l] = (q0 & 255) | ((q1 & 255) << 8) | ((q2 & 255) << 16)
                     | ((q3 & 255) << 24);
        }
        {
            int q0 = __float2int_rn(v1.x * rs), q1 = __float2int_rn(v1.y * rs);
            int q2 = __float2int_rn(v1.z * rs), q3 = __float2int_rn(v1.w * rs);
            d32[l + 32] = (q0 & 255) | ((q1 & 255) << 8) | ((q2 & 255) << 16)
                          | ((q3 & 255) << 24);
        }
        if (l == 0) sdst[p] = m * (1.0f / 127.0f);
    }
    // zero this CTA's slice of the global accumulators (16 + 16 words)
    if (tid < 16)       g_Row[L * 16 + tid] = 0.0f;
    else if (tid < 32)  g_Col[L * 16 + tid - 16] = 0.0f;

    // ================= grid barrier (monotone ticket) ======================
    __threadfence();           // release: quant writes visible before arrive
    __syncthreads();
    if (tid == 0) {
        const unsigned t = atomicAdd(&g_bar, 1u);
        const unsigned target = (t / NCTAS + 1u) * NCTAS;
        while (*(volatile unsigned*)&g_bar < target) { }
    }
    __syncthreads();
    __threadfence();           // acquire

    // ================= phase 2: gemm (R13-validated) =======================
    const int ld_row = tid >> 3;
    const int ld_seg = tid & 7;

    auto issue_chunk = [&](int c, uint32_t aoff, uint32_t boff) {
#pragma unroll
        for (int i = 0; i < 2; i++) {
            const int row = ld_row + 64 * i;
            cpasync16(sbase + aoff + row * ROWC + ld_seg * 16,
                      &g_Aq[(size_t)(r0 + row) * DFEAT + c * 128 + ld_seg * 16]);
        }
#pragma unroll
        for (int i = 0; i < 4; i++) {
            const int row = ld_row + 64 * i;
            cpasync16(sbase + boff + row * ROWC + ld_seg * 16,
                      &g_Bq[(size_t)(c0 + row) * DFEAT + c * 128 + ld_seg * 16]);
        }
        CP_COMMIT();
    };

    issue_chunk(0, SM_A0, SM_B0);
    issue_chunk(1, SM_A1, SM_B1);

    if (tid < 128) sA_s[tid] = g_SA[r0 + tid];
    if (tid < 256) sB_s[tid] = g_SB[c0 + tid];

    const int a_row = (l & 7) + 8 * ((l >> 3) & 1);
    const int a_kb  = 16 * ((l >> 4) & 1);
    const int b_row = (l & 7) + 8 * ((l >> 4) & 1);
    const int b_kb  = 16 * ((l >> 3) & 1);
    const uint32_t aRel = (uint32_t)(wm * 32 + a_row) * ROWC + a_kb;
    const uint32_t bRel = (uint32_t)(wn * 64 + b_row) * ROWC + b_kb;

    int acc[2][8][4];
#pragma unroll
    for (int mt = 0; mt < 2; mt++)
#pragma unroll
        for (int nt = 0; nt < 8; nt++)
#pragma unroll
            for (int r = 0; r < 4; r++) acc[mt][nt][r] = 0;

    auto compute_chunk = [&](uint32_t aoff, uint32_t boff) {
        const uint32_t aAddr0 = sbase + aoff + aRel;
        const uint32_t bAddr0 = sbase + boff + bRel;
#pragma unroll
        for (int kk = 0; kk < 4; kk++) {
            const uint32_t koff = (uint32_t)kk * 32;
            uint32_t a[2][4];
            ldsm_x4(a[0], aAddr0 + koff);
            ldsm_x4(a[1], aAddr0 + 16 * ROWC + koff);
            uint32_t b[8][2];
#pragma unroll
            for (int q = 0; q < 4; q++) {
                uint32_t t[4];
                ldsm_x4(t, bAddr0 + (uint32_t)(q * 16) * ROWC + koff);
                b[2 * q][0] = t[0];      b[2 * q][1] = t[1];
                b[2 * q + 1][0] = t[2];  b[2 * q + 1][1] = t[3];
            }
#pragma unroll
            for (int mt = 0; mt < 2; mt++)
#pragma unroll
                for (int nt = 0; nt < 8; nt++)
                    imma16832(acc[mt][nt], a[mt], b[nt]);
        }
    };

    CP_WAIT(1); __syncthreads();
    compute_chunk(SM_A0, SM_B0);
    CP_WAIT(0); __syncthreads();
    compute_chunk(SM_A1, SM_B1);

    // ---- epilogue: unmasked exp row/col sums ----
    float srow[2][2], srowl[2][2], scol[8][2];
#pragma unroll
    for (int mt = 0; mt < 2; mt++)
#pragma unroll
        for (int h = 0; h < 2; h++) {
            srow[mt][h]  = sA_s[wm * 32 + mt * 16 + h * 8 + (l >> 2)]
                           * (1.0f / 128.0f);
            srowl[mt][h] = srow[mt][h] * LOG2E;
        }
#pragma unroll
    for (int nt = 0; nt < 8; nt++)
#pragma unroll
        for (int j = 0; j < 2; j++)
            scol[nt][j] = sB_s[wn * 64 + nt * 8 + 2 * (l & 3) + j];

    float rowp[2][2];
    float colp[8][2];
#pragma unroll
    for (int mt = 0; mt < 2; mt++)
#pragma unroll
        for (int h = 0; h < 2; h++) rowp[mt][h] = 0.0f;
#pragma unroll
    for (int nt = 0; nt < 8; nt++)
#pragma unroll
        for (int j = 0; j < 2; j++) colp[nt][j] = 0.0f;

#pragma unroll
    for (int mt = 0; mt < 2; mt++) {
#pragma unroll
        for (int h = 0; h < 2; h++) {
#pragma unroll
            for (int nt = 0; nt < 8; nt++) {
#pragma unroll
                for (int j = 0; j < 2; j++) {
                    const float accf = (float)acc[mt][nt][2 * h + j];
                    const float x = ex2f(fmaf(accf * srowl[mt][h],
                                              scol[nt][j], LOG2E));
                    rowp[mt][h] += x;
                    colp[nt][j] += x;
                }
            }
        }
    }

    // ---- exclusion / diagonal side loops (uniform CTA predicates) ----
    if (bx == by) {
#pragma unroll
        for (int mt = 0; mt < 2; mt++)
#pragma unroll
            for (int h = 0; h < 2; h++) {
                const int gr = r0 + wm * 32 + mt * 16 + h * 8 + (l >> 2);
#pragma unroll
                for (int nt = 0; nt < 8; nt++)
#pragma unroll
                    for (int j = 0; j < 2; j++) {
                        const int gc = c0 + wn * 64 + nt * 8 + 2 * (l & 3) + j;
                        if (gc == 2 * gr + 1) {
                            const float accf = (float)acc[mt][nt][2 * h + j];
                            g_ExclR[gr] = ex2f(fmaf(accf * srowl[mt][h],
                                                    scol[nt][j], LOG2E));
                        }
                    }
            }
    }
    if (bx == (by >> 2)) {
#pragma unroll
        for (int mt = 0; mt < 2; mt++)
#pragma unroll
            for (int h = 0; h < 2; h++) {
                const int gr = r0 + wm * 32 + mt * 16 + h * 8 + (l >> 2);
#pragma unroll
                for (int nt = 0; nt < 8; nt++)
#pragma unroll
                    for (int j = 0; j < 2; j++) {
                        const int gc = c0 + wn * 64 + nt * 8 + 2 * (l & 3) + j;
                        if (gr == 2 * gc) {
                            const float accf = (float)acc[mt][nt][2 * h + j];
                            g_ExclC[gc] = ex2f(fmaf(accf * srowl[mt][h],
                                                    scol[nt][j], LOG2E));
                        }
                    }
            }
    }
    if (bx == (by >> 1)) {
#pragma unroll
        for (int mt = 0; mt < 2; mt++)
#pragma unroll
            for (int h = 0; h < 2; h++) {
                const int gr = r0 + wm * 32 + mt * 16 + h * 8 + (l >> 2);
#pragma unroll
                for (int nt = 0; nt < 8; nt++)
#pragma unroll
                    for (int j = 0; j < 2; j++) {
                        const int gc = c0 + wn * 64 + nt * 8 + 2 * (l & 3) + j;
                        if (gr == gc) {
                            const float accf = (float)acc[mt][nt][2 * h + j];
                            g_Dpos[gr] = accf * srow[mt][h] * scol[nt][j];
                        }
                    }
            }
    }

    // ---- reduction: shfl + plain STS partials, then REDG to global ----
#pragma unroll
    for (int mt = 0; mt < 2; mt++) {
#pragma unroll
        for (int h = 0; h < 2; h++) {
            float v = rowp[mt][h];
            v += __shfl_xor_sync(0xFFFFFFFFu, v, 1);
            v += __shfl_xor_sync(0xFFFFFFFFu, v, 2);
            if ((l & 3) == 0)
                rpart[wn * 128 + wm * 32 + mt * 16 + h * 8 + (l >> 2)] = v;
        }
    }
#pragma unroll
    for (int nt = 0; nt < 8; nt++) {
#pragma unroll
        for (int j = 0; j < 2; j++) {
            float v = colp[nt][j];
            v += __shfl_xor_sync(0xFFFFFFFFu, v, 4);
            v += __shfl_xor_sync(0xFFFFFFFFu, v, 8);
            v += __shfl_xor_sync(0xFFFFFFFFu, v, 16);
            if (l < 4)
                cpart[wm * 256 + wn * 64 + nt * 8 + 2 * l + j] = v;
        }
    }
    __syncthreads();

    if (tid < 128) {
        atomicAdd(&g_Row[r0 + tid], rpart[tid] + rpart[128 + tid]
                                  + rpart[256 + tid] + rpart[384 + tid]);
    } else if (tid < 384) {
        const int c = tid - 128;
        atomicAdd(&g_Col[c0 + c], cpart[c] + cpart[256 + c]
                                + cpart[512 + c] + cpart[768 + c]);
    }

    // ---- last-CTA finalize (monotone ticket, slim read set) ----
    __threadfence();
    __syncthreads();
    __shared__ unsigned int s_last;
    if (tid == 0)
        s_last = ((atomicAdd(&g_done, 1u) % NCTAS) == (unsigned)(NCTAS - 1))
                 ? 1u : 0u;
    __syncthreads();

    if (s_last) {
        __threadfence();
        float* red = (float*)(smem + SM_RED);
        float acc2 = 0.0f;
#pragma unroll
        for (int rep = 0; rep < 4; rep++) {
            const int p = tid + rep * 512;
            const float neg = g_Row[p] + g_Col[p] - g_ExclR[p] - g_ExclC[p];
            const float J = logf(1e-8f + neg) - g_Dpos[p];
            const float t = fmaxf(J, 0.0f);
            acc2 += t * t;
        }
        red[tid] = acc2;
        __syncthreads();
        for (int off = 256; off > 0; off >>= 1) {
            if (tid < off) red[tid] += red[tid + off];
            __syncthreads();
        }
        if (tid == 0) out[0] = red[0] * (1.0f / 4096.0f);
    }
}

// ---------------------------------------------------------------------------
extern "C" void kernel_launch(void* const* d_in, const int* in_sizes, int n_in,
                              void* d_out, int out_size) {
    const float* X = (const float*)d_in[0];
    float* out = (float*)d_out;

    cudaFuncSetAttribute(sml_fused, cudaFuncAttributeMaxDynamicSharedMemorySize,
                         SMEM_TOTAL);
    dim3 grid(NBX, NBY);   // 128 CTAs, 1/SM, co-resident single wave
    sml_fused<<<grid, 512, SMEM_TOTAL>>>(X, out);
}

// round 15
// speedup vs baseline: 1.1016x; 1.1016x over previous
#include <cuda_runtime.h>
#include <cstdint>
#include <math.h>

#define NP    2048
#define DFEAT 256
#define BTM   128
#define BTN   256
#define NBX   (NP / BTN)       // 8
#define NBY   (NP / BTM)       // 16
#define NCTAS (NBX * NBY)      // 128 -> 1 CTA/SM, balanced single wave
#define LOG2E 1.4426950408889634f

// K (256 int8) streamed in 2 chunks of 128B; rows padded to 144B
#define ROWC    144
#define A_CHUNK (BTM * ROWC)   // 18432
#define B_CHUNK (BTN * ROWC)   // 36864
#define SM_A0   0
#define SM_A1   A_CHUNK
#define SM_B0   (2 * A_CHUNK)
#define SM_B1   (2 * A_CHUNK + B_CHUNK)
#define SM_SA   (2 * A_CHUNK + 2 * B_CHUNK)   // sA[128] floats
#define SM_SB   (SM_SA + 512)                 // sB[256] floats
#define SM_RP   (SM_SB + 1024)                // rpart[4][128]
#define SM_CP   (SM_RP + 2048)                // cpart[4][256]
#define SM_RED  (SM_CP + 4096)                // red[512]
#define SMEM_TOTAL (SM_RED + 2048)            // 120320 B

// -------- device scratch --------
__device__ __align__(16) int8_t g_Aq[NP * DFEAT];
__device__ __align__(16) int8_t g_Bq[NP * DFEAT];
__device__ float g_SA[NP];
__device__ float g_SB[NP];
__device__ float g_Row[NP];     // zeroed by quant kernel each replay
__device__ float g_Col[NP];
__device__ float g_Dpos[NP];
__device__ float g_ExclR[NP];   // p>=1024 never written, stays 0
__device__ float g_ExclC[NP];
__device__ unsigned int g_done = 0;   // monotone finalize ticket

static __device__ __forceinline__ uint32_t smem_u32(const void* p) {
    return (uint32_t)__cvta_generic_to_shared((void*)p);
}

static __device__ __forceinline__ void cpasync16(uint32_t dst, const void* src) {
    asm volatile("cp.async.cg.shared.global [%0], [%1], 16;"
                 :: "r"(dst), "l"(src));
}
#define CP_COMMIT() asm volatile("cp.async.commit_group;" ::: "memory")
#define CP_WAIT(N)  asm volatile("cp.async.wait_group %0;" :: "n"(N) : "memory")

static __device__ __forceinline__ void ldsm_x4(uint32_t* r, uint32_t addr) {
    asm volatile("ldmatrix.sync.aligned.m8n8.x4.shared.b16 {%0,%1,%2,%3}, [%4];"
                 : "=r"(r[0]), "=r"(r[1]), "=r"(r[2]), "=r"(r[3]) : "r"(addr));
}

static __device__ __forceinline__ void imma16832(int* c, const uint32_t* a,
                                                 const uint32_t* b) {
    asm volatile(
        "mma.sync.aligned.m16n8k32.row.col.s32.s8.s8.s32 "
        "{%0,%1,%2,%3}, {%4,%5,%6,%7}, {%8,%9}, {%0,%1,%2,%3};"
        : "+r"(c[0]), "+r"(c[1]), "+r"(c[2]), "+r"(c[3])
        : "r"(a[0]), "r"(a[1]), "r"(a[2]), "r"(a[3]), "r"(b[0]), "r"(b[1]));
}

static __device__ __forceinline__ float ex2f(float a) {
    float r;
    asm("ex2.approx.f32 %0, %1;" : "=f"(r) : "f"(a));
    return r;
}

// ---------------------------------------------------------------------------
// Kernel 1: per-row int8 quantization + even/odd deinterleave (validated),
// plus zeroing of the global accumulators (visible to K2 via launch boundary).
// ---------------------------------------------------------------------------
__global__ void sml_quant(const float* __restrict__ X) {
    // zero accumulators: first 8 blocks x 256 threads cover 2048 entries
    if (blockIdx.x < 8) {
        const int p = blockIdx.x * 256 + threadIdx.x;
        g_Row[p] = 0.0f;
        g_Col[p] = 0.0f;
    }

    const int gw = (blockIdx.x * blockDim.x + threadIdx.x) >> 5;
    const int l = threadIdx.x & 31;
    const float4* src = (const float4*)X + (size_t)gw * 64;
    const float4 v0 = src[l];
    const float4 v1 = src[l + 32];

    float m = fmaxf(fmaxf(fabsf(v0.x), fabsf(v0.y)),
                    fmaxf(fabsf(v0.z), fabsf(v0.w)));
    m = fmaxf(m, fmaxf(fmaxf(fabsf(v1.x), fabsf(v1.y)),
                       fmaxf(fabsf(v1.z), fabsf(v1.w))));
#pragma unroll
    for (int mk = 16; mk > 0; mk >>= 1)
        m = fmaxf(m, __shfl_xor_sync(0xFFFFFFFFu, m, mk));
    m = fmaxf(m, 1e-20f);
    const float rs = 127.0f / m;

    const int p = gw >> 1;
    int8_t* dstrow;
    float* sdst;
    if (gw & 1) { dstrow = g_Bq + (size_t)p * DFEAT; sdst = g_SB; }
    else        { dstrow = g_Aq + (size_t)p * DFEAT; sdst = g_SA; }

    uint32_t* d32 = (uint32_t*)dstrow;
    {
        int q0 = __float2int_rn(v0.x * rs), q1 = __float2int_rn(v0.y * rs);
        int q2 = __float2int_rn(v0.z * rs), q3 = __float2int_rn(v0.w * rs);
        d32[l] = (q0 & 255) | ((q1 & 255) << 8) | ((q2 & 255) << 16)
                 | ((q3 & 255) << 24);
    }
    {
        int q0 = __float2int_rn(v1.x * rs), q1 = __float2int_rn(v1.y * rs);
        int q2 = __float2int_rn(v1.z * rs), q3 = __float2int_rn(v1.w * rs);
        d32[l + 32] = (q0 & 255) | ((q1 & 255) << 8) | ((q2 & 255) << 16)
                      | ((q3 & 255) << 24);
    }
    if (l == 0) sdst[p] = m * (1.0f / 127.0f);
}

// ---------------------------------------------------------------------------
// Kernel 2: R13-validated IMMA gemm + unmasked exp epilogue; partials REDG'd
// into g_Row/g_Col; slim last-CTA finalize.
// ---------------------------------------------------------------------------
__global__ __launch_bounds__(512, 1)
void sml_gemm(float* __restrict__ out) {
    extern __shared__ char smem[];
    const uint32_t sbase = smem_u32(smem);
    float* sA_s  = (float*)(smem + SM_SA);
    float* sB_s  = (float*)(smem + SM_SB);
    float* rpart = (float*)(smem + SM_RP);
    float* cpart = (float*)(smem + SM_CP);

    const int tid = threadIdx.x;
    const int wid = tid >> 5;
    const int l   = tid & 31;
    const int wm  = wid & 3;
    const int wn  = wid >> 2;
    const int bx = blockIdx.x, by = blockIdx.y;
    const int r0 = by * BTM, c0 = bx * BTN;

    const int ld_row = tid >> 3;
    const int ld_seg = tid & 7;

    auto issue_chunk = [&](int c, uint32_t aoff, uint32_t boff) {
#pragma unroll
        for (int i = 0; i < 2; i++) {
            const int row = ld_row + 64 * i;
            cpasync16(sbase + aoff + row * ROWC + ld_seg * 16,
                      &g_Aq[(size_t)(r0 + row) * DFEAT + c * 128 + ld_seg * 16]);
        }
#pragma unroll
        for (int i = 0; i < 4; i++) {
            const int row = ld_row + 64 * i;
            cpasync16(sbase + boff + row * ROWC + ld_seg * 16,
                      &g_Bq[(size_t)(c0 + row) * DFEAT + c * 128 + ld_seg * 16]);
        }
        CP_COMMIT();
    };

    issue_chunk(0, SM_A0, SM_B0);
    issue_chunk(1, SM_A1, SM_B1);

    if (tid < 128) sA_s[tid] = g_SA[r0 + tid];
    if (tid < 256) sB_s[tid] = g_SB[c0 + tid];

    const int a_row = (l & 7) + 8 * ((l >> 3) & 1);
    const int a_kb  = 16 * ((l >> 4) & 1);
    const int b_row = (l & 7) + 8 * ((l >> 4) & 1);
    const int b_kb  = 16 * ((l >> 3) & 1);
    const uint32_t aRel = (uint32_t)(wm * 32 + a_row) * ROWC + a_kb;
    const uint32_t bRel = (uint32_t)(wn * 64 + b_row) * ROWC + b_kb;

    int acc[2][8][4];
#pragma unroll
    for (int mt = 0; mt < 2; mt++)
#pragma unroll
        for (int nt = 0; nt < 8; nt++)
#pragma unroll
            for (int r = 0; r < 4; r++) acc[mt][nt][r] = 0;

    auto compute_chunk = [&](uint32_t aoff, uint32_t boff) {
        const uint32_t aAddr0 = sbase + aoff + aRel;
        const uint32_t bAddr0 = sbase + boff + bRel;
#pragma unroll
        for (int kk = 0; kk < 4; kk++) {
            const uint32_t koff = (uint32_t)kk * 32;
            uint32_t a[2][4];
            ldsm_x4(a[0], aAddr0 + koff);
            ldsm_x4(a[1], aAddr0 + 16 * ROWC + koff);
            uint32_t b[8][2];
#pragma unroll
            for (int q = 0; q < 4; q++) {
                uint32_t t[4];
                ldsm_x4(t, bAddr0 + (uint32_t)(q * 16) * ROWC + koff);
                b[2 * q][0] = t[0];      b[2 * q][1] = t[1];
                b[2 * q + 1][0] = t[2];  b[2 * q + 1][1] = t[3];
            }
#pragma unroll
            for (int mt = 0; mt < 2; mt++)
#pragma unroll
                for (int nt = 0; nt < 8; nt++)
                    imma16832(acc[mt][nt], a[mt], b[nt]);
        }
    };

    CP_WAIT(1); __syncthreads();
    compute_chunk(SM_A0, SM_B0);
    CP_WAIT(0); __syncthreads();
    compute_chunk(SM_A1, SM_B1);

    // ---- epilogue: unmasked exp row/col sums ----
    float srow[2][2], srowl[2][2], scol[8][2];
#pragma unroll
    for (int mt = 0; mt < 2; mt++)
#pragma unroll
        for (int h = 0; h < 2; h++) {
            srow[mt][h]  = sA_s[wm * 32 + mt * 16 + h * 8 + (l >> 2)]
                           * (1.0f / 128.0f);
            srowl[mt][h] = srow[mt][h] * LOG2E;
        }
#pragma unroll
    for (int nt = 0; nt < 8; nt++)
#pragma unroll
        for (int j = 0; j < 2; j++)
            scol[nt][j] = sB_s[wn * 64 + nt * 8 + 2 * (l & 3) + j];

    float rowp[2][2];
    float colp[8][2];
#pragma unroll
    for (int mt = 0; mt < 2; mt++)
#pragma unroll
        for (int h = 0; h < 2; h++) rowp[mt][h] = 0.0f;
#pragma unroll
    for (int nt = 0; nt < 8; nt++)
#pragma unroll
        for (int j = 0; j < 2; j++) colp[nt][j] = 0.0f;

#pragma unroll
    for (int mt = 0; mt < 2; mt++) {
#pragma unroll
        for (int h = 0; h < 2; h++) {
#pragma unroll
            for (int nt = 0; nt < 8; nt++) {
#pragma unroll
                for (int j = 0; j < 2; j++) {
                    const float accf = (float)acc[mt][nt][2 * h + j];
                    const float x = ex2f(fmaf(accf * srowl[mt][h],
                                              scol[nt][j], LOG2E));
                    rowp[mt][h] += x;
                    colp[nt][j] += x;
                }
            }
        }
    }

    // ---- exclusion / diagonal side loops (uniform CTA predicates) ----
    if (bx == by) {
#pragma unroll
        for (int mt = 0; mt < 2; mt++)
#pragma unroll
            for (int h = 0; h < 2; h++) {
                const int gr = r0 + wm * 32 + mt * 16 + h * 8 + (l >> 2);
#pragma unroll
                for (int nt = 0; nt < 8; nt++)
#pragma unroll
                    for (int j = 0; j < 2; j++) {
                        const int gc = c0 + wn * 64 + nt * 8 + 2 * (l & 3) + j;
                        if (gc == 2 * gr + 1) {
                            const float accf = (float)acc[mt][nt][2 * h + j];
                            g_ExclR[gr] = ex2f(fmaf(accf * srowl[mt][h],
                                                    scol[nt][j], LOG2E));
                        }
                    }
            }
    }
    if (bx == (by >> 2)) {
#pragma unroll
        for (int mt = 0; mt < 2; mt++)
#pragma unroll
            for (int h = 0; h < 2; h++) {
                const int gr = r0 + wm * 32 + mt * 16 + h * 8 + (l >> 2);
#pragma unroll
                for (int nt = 0; nt < 8; nt++)
#pragma unroll
                    for (int j = 0; j < 2; j++) {
                        const int gc = c0 + wn * 64 + nt * 8 + 2 * (l & 3) + j;
                        if (gr == 2 * gc) {
                            const float accf = (float)acc[mt][nt][2 * h + j];
                            g_ExclC[gc] = ex2f(fmaf(accf * srowl[mt][h],
                                                    scol[nt][j], LOG2E));
                        }
                    }
            }
    }
    if (bx == (by >> 1)) {
#pragma unroll
        for (int mt = 0; mt < 2; mt++)
#pragma unroll
            for (int h = 0; h < 2; h++) {
                const int gr = r0 + wm * 32 + mt * 16 + h * 8 + (l >> 2);
#pragma unroll
                for (int nt = 0; nt < 8; nt++)
#pragma unroll
                    for (int j = 0; j < 2; j++) {
                        const int gc = c0 + wn * 64 + nt * 8 + 2 * (l & 3) + j;
                        if (gr == gc) {
                            const float accf = (float)acc[mt][nt][2 * h + j];
                            g_Dpos[gr] = accf * srow[mt][h] * scol[nt][j];
                        }
                    }
            }
    }

    // ---- reduction: shfl + plain STS partials, then REDG to global ----
#pragma unroll
    for (int mt = 0; mt < 2; mt++) {
#pragma unroll
        for (int h = 0; h < 2; h++) {
            float v = rowp[mt][h];
            v += __shfl_xor_sync(0xFFFFFFFFu, v, 1);
            v += __shfl_xor_sync(0xFFFFFFFFu, v, 2);
            if ((l & 3) == 0)
                rpart[wn * 128 + wm * 32 + mt * 16 + h * 8 + (l >> 2)] = v;
        }
    }
#pragma unroll
    for (int nt = 0; nt < 8; nt++) {
#pragma unroll
        for (int j = 0; j < 2; j++) {
            float v = colp[nt][j];
            v += __shfl_xor_sync(0xFFFFFFFFu, v, 4);
            v += __shfl_xor_sync(0xFFFFFFFFu, v, 8);
            v += __shfl_xor_sync(0xFFFFFFFFu, v, 16);
            if (l < 4)
                cpart[wm * 256 + wn * 64 + nt * 8 + 2 * l + j] = v;
        }
    }
    __syncthreads();

    if (tid < 128) {
        atomicAdd(&g_Row[r0 + tid], rpart[tid] + rpart[128 + tid]
                                  + rpart[256 + tid] + rpart[384 + tid]);
    } else if (tid < 384) {
        const int c = tid - 128;
        atomicAdd(&g_Col[c0 + c], cpart[c] + cpart[256 + c]
                                + cpart[512 + c] + cpart[768 + c]);
    }

    // ---- last-CTA slim finalize (monotone ticket) ----
    __threadfence();
    __syncthreads();
    __shared__ unsigned int s_last;
    if (tid == 0)
        s_last = ((atomicAdd(&g_done, 1u) % NCTAS) == (unsigned)(NCTAS - 1))
                 ? 1u : 0u;
    __syncthreads();

    if (s_last) {
        __threadfence();
        float* red = (float*)(smem + SM_RED);
        float acc2 = 0.0f;
#pragma unroll
        for (int rep = 0; rep < 4; rep++) {
            const int p = tid + rep * 512;
            const float neg = g_Row[p] + g_Col[p] - g_ExclR[p] - g_ExclC[p];
            const float J = logf(1e-8f + neg) - g_Dpos[p];
            const float t = fmaxf(J, 0.0f);
            acc2 += t * t;
        }
        red[tid] = acc2;
        __syncthreads();
        for (int off = 256; off > 0; off >>= 1) {
            if (tid < off) red[tid] += red[tid + off];
            __syncthreads();
        }
        if (tid == 0) out[0] = red[0] * (1.0f / 4096.0f);
    }
}

// ---------------------------------------------------------------------------
extern "C" void kernel_launch(void* const* d_in, const int* in_sizes, int n_in,
                              void* d_out, int out_size) {
    const float* X = (const float*)d_in[0];
    float* out = (float*)d_out;

    sml_quant<<<512, 256>>>(X);

    cudaFuncSetAttribute(sml_gemm, cudaFuncAttributeMaxDynamicSharedMemorySize,
                         SMEM_TOTAL);
    dim3 grid(NBX, NBY);   // 128 CTAs, 1/SM, balanced single wave
    sml_gemm<<<grid, 512, SMEM_TOTAL>>>(out);
}